// round 14
// baseline (speedup 1.0000x reference)
#include <cuda_runtime.h>
#include <cuda_bf16.h>
#include <stdint.h>
#include <math.h>

#define NE   800000
#define NND  100000
#define HH   128
#define KIN  256
#define FF   512
#define TE   128
#define SINV (1.0f/30.0f)

// scratch: aggregated messages (51.2 MB) + prepped bf16 split weights
__device__ float g_dh[(size_t)NND * HH];
__device__ __align__(16) unsigned char g_wprep[8 * 32768];    // edge: 8 x 32KB K64-chunks
__device__ __align__(16) unsigned char g_nwprep[8 * 65536];   // node D1(4) + D2(4)

// ===========================================================================
// helpers
// ===========================================================================
__device__ __forceinline__ uint32_t smem_u32(const void* p) {
    uint32_t a;
    asm("{ .reg .u64 t; cvta.to.shared.u64 t, %1; cvt.u32.u64 %0, t; }"
        : "=r"(a) : "l"(p));
    return a;
}

#define LDSM_X4(r0, r1, r2, r3, addr) \
    asm volatile("ldmatrix.sync.aligned.m8n8.x4.shared.b16 {%0,%1,%2,%3}, [%4];" \
        : "=r"(r0), "=r"(r1), "=r"(r2), "=r"(r3) : "r"(addr))

#define LDSM_X4T(r0, r1, r2, r3, addr) \
    asm volatile("ldmatrix.sync.aligned.m8n8.x4.trans.shared.b16 {%0,%1,%2,%3}, [%4];" \
        : "=r"(r0), "=r"(r1), "=r"(r2), "=r"(r3) : "r"(addr))

#define MMA_BF16(d, a, b0, b1) \
    asm volatile("mma.sync.aligned.m16n8k16.row.col.f32.bf16.bf16.f32 " \
        "{%0,%1,%2,%3}, {%4,%5,%6,%7}, {%8,%9}, {%0,%1,%2,%3};" \
        : "+f"((d)[0]), "+f"((d)[1]), "+f"((d)[2]), "+f"((d)[3]) \
        : "r"((a)[0]), "r"((a)[1]), "r"((a)[2]), "r"((a)[3]), "r"(b0), "r"(b1))

#define CP_WAIT(n) asm volatile("cp.async.wait_group %0;" :: "n"(n) : "memory")

// 64KB weight chunk copy (node kernel) — per-thread 16 x 16B + commit
__device__ __forceinline__ void cp_w(uint32_t dsts, const unsigned char* src, int tid) {
#pragma unroll
    for (int i = 0; i < 16; i++) {
        uint32_t o = (uint32_t)(tid + 256 * i) * 16u;
        asm volatile("cp.async.cg.shared.global [%0], [%1], 16;"
                     :: "r"(dsts + o), "l"(src + o) : "memory");
    }
    asm volatile("cp.async.commit_group;" ::: "memory");
}

// 32KB weight chunk copy (edge kernel) — per-thread 8 x 16B + commit
__device__ __forceinline__ void cp_w32(uint32_t dsts, const unsigned char* src, int tid) {
#pragma unroll
    for (int i = 0; i < 8; i++) {
        uint32_t o = (uint32_t)(tid + 256 * i) * 16u;
        asm volatile("cp.async.cg.shared.global [%0], [%1], 16;"
                     :: "r"(dsts + o), "l"(src + o) : "memory");
    }
    asm volatile("cp.async.commit_group;" ::: "memory");
}

__device__ __forceinline__ uint32_t pack_bf2(float v0, float v1) {
    __nv_bfloat16 h0 = __float2bfloat16(v0), h1 = __float2bfloat16(v1);
    return (uint32_t)__bfloat16_as_ushort(h0) | ((uint32_t)__bfloat16_as_ushort(h1) << 16);
}

// ===========================================================================
// EDGE machinery — 128x128 tile, warps 4x2, K=64 chunks
// A chunk slab: 128 rows x 64 k bf16 = 16KB. W chunk: [hi n0-63 8K][hi n64-127 8K]
// [lo n0-63 8K][lo n64-127 8K] = 32KB.
// ===========================================================================
__device__ __forceinline__ void mma_chunk64e(float (*acc)[8][4], uint32_t ahi, uint32_t alo,
                                             uint32_t wb, int warpM, int warpN, int lane) {
#pragma unroll
    for (int pass = 0; pass < 3; pass++) {
        uint32_t ab = (pass == 2) ? alo : ahi;
        uint32_t bb = wb + ((pass == 1) ? 16384u : 0u) + (uint32_t)warpN * 8192u;
#pragma unroll
        for (int s = 0; s < 4; s++) {
            uint32_t a[2][4];
#pragma unroll
            for (int mi = 0; mi < 2; mi++) {
                int row = warpM * 32 + mi * 16 + (lane & 15);
                uint32_t off = ((uint32_t)(row >> 3) << 10) + ((uint32_t)(row & 7) << 7)
                             + (uint32_t)(s * 32 + ((lane >> 4) << 4));
                off ^= (off >> 3) & 0x70;
                LDSM_X4(a[mi][0], a[mi][1], a[mi][2], a[mi][3], ab + off);
            }
            int k = s * 16 + (lane & 15);
            uint32_t koff = ((uint32_t)(k >> 3) << 10) + ((uint32_t)(k & 7) << 7)
                          + ((uint32_t)(lane >> 4) << 4);
#pragma unroll
            for (int bp = 0; bp < 2; bp++) {          // 2 halves: live b regs = 8
                uint32_t b[2][4];
#pragma unroll
                for (int bi = 0; bi < 2; bi++) {
                    uint32_t off = koff + (uint32_t)(bp * 2 + bi) * 32u;
                    off ^= (off >> 3) & 0x70;
                    LDSM_X4T(b[bi][0], b[bi][1], b[bi][2], b[bi][3], bb + off);
                }
#pragma unroll
                for (int mi = 0; mi < 2; mi++)
#pragma unroll
                    for (int bi = 0; bi < 2; bi++)
#pragma unroll
                        for (int hf = 0; hf < 2; hf++)
                            MMA_BF16(acc[mi][bp * 4 + bi * 2 + hf], a[mi],
                                     b[bi][hf * 2], b[bi][hf * 2 + 1]);
            }
        }
    }
}

// edge layer epilogue: relu(acc+bias) -> split hi/lo -> M slabs in A region.
// A region layout: [hi chunk0 16K][hi chunk1 16K][lo chunk0 16K][lo chunk1 16K]
__device__ __forceinline__ void epi_acte(float (*acc)[8][4], uint8_t* abase,
                                         const float* bias, int warpM, int warpN, int lane) {
    uint32_t slab = (uint32_t)warpN * 16384u;
#pragma unroll
    for (int mi = 0; mi < 2; mi++) {
#pragma unroll
        for (int nt = 0; nt < 8; nt++) {
            int r0 = warpM * 32 + mi * 16 + (lane >> 2);
            int kk = nt * 8 + (lane & 3) * 2;
            int n  = warpN * 64 + kk;
            float b0v = bias[n], b1v = bias[n + 1];
#pragma unroll
            for (int hh = 0; hh < 2; hh++) {
                int r = r0 + hh * 8;
                float v0 = fmaxf(acc[mi][nt][hh * 2 + 0] + b0v, 0.f);
                float v1 = fmaxf(acc[mi][nt][hh * 2 + 1] + b1v, 0.f);
                __nv_bfloat16 h0 = __float2bfloat16(v0), h1 = __float2bfloat16(v1);
                uint32_t hp = (uint32_t)__bfloat16_as_ushort(h0)
                            | ((uint32_t)__bfloat16_as_ushort(h1) << 16);
                uint32_t lp = pack_bf2(v0 - __bfloat162float(h0), v1 - __bfloat162float(h1));
                uint32_t off = ((uint32_t)(r >> 3) << 10) + ((uint32_t)(r & 7) << 7)
                             + (uint32_t)kk * 2;
                off ^= (off >> 3) & 0x70;
                *(uint32_t*)(abase + slab + off) = hp;
                *(uint32_t*)(abase + 32768 + slab + off) = lp;
            }
            acc[mi][nt][0] = 0.f; acc[mi][nt][1] = 0.f;
            acc[mi][nt][2] = 0.f; acc[mi][nt][3] = 0.f;
        }
    }
}

// Stage 128 edges x 64 k of hE (fp32 -> bf16 hi/lo) into one A chunk slot.
__device__ __forceinline__ void stage_A64(uint8_t* smb, uint32_t of_hi, uint32_t of_lo,
                                          const float* __restrict__ hE,
                                          size_t e0, int kc, int tid) {
#pragma unroll
    for (int it = 0; it < 8; it++) {
        int idx = tid + 256 * it;           // 0..2047 (128 rows x 16 float4)
        int r = idx >> 4, c4 = idx & 15;
        float4 v = *(const float4*)(hE + (e0 + r) * KIN + kc + c4 * 4);
        __nv_bfloat16 h0 = __float2bfloat16(v.x), h1 = __float2bfloat16(v.y);
        __nv_bfloat16 h2 = __float2bfloat16(v.z), h3 = __float2bfloat16(v.w);
        uint32_t hA = (uint32_t)__bfloat16_as_ushort(h0) | ((uint32_t)__bfloat16_as_ushort(h1) << 16);
        uint32_t hB = (uint32_t)__bfloat16_as_ushort(h2) | ((uint32_t)__bfloat16_as_ushort(h3) << 16);
        uint32_t lA = pack_bf2(v.x - __bfloat162float(h0), v.y - __bfloat162float(h1));
        uint32_t lB = pack_bf2(v.z - __bfloat162float(h2), v.w - __bfloat162float(h3));
        uint32_t off = ((uint32_t)(r >> 3) << 10) + ((uint32_t)(r & 7) << 7) + ((uint32_t)c4 << 3);
        off ^= (off >> 3) & 0x70;
        *(uint2*)(smb + of_hi + off) = make_uint2(hA, hB);
        *(uint2*)(smb + of_lo + off) = make_uint2(lA, lB);
    }
}

// ===========================================================================
// NODE machinery — 64x128 tile, warps 2x4 (validated round 12, unchanged)
// ===========================================================================
__device__ __forceinline__ void mma_chunk64(float (*acc)[4][4], uint32_t ahi, uint32_t alo,
                                            uint32_t wb, int warpM, int warpN, int lane) {
    const uint32_t colbase = (uint32_t)(warpN & 1) * 64u;
    const uint32_t wslab   = (uint32_t)(warpN >> 1) * 16384u;
#pragma unroll
    for (int pass = 0; pass < 3; pass++) {
        uint32_t ab = (pass == 2) ? alo : ahi;
        uint32_t bb = wb + ((pass == 1) ? 32768u : 0u) + wslab;
#pragma unroll
        for (int s = 0; s < 8; s++) {
            uint32_t a[2][4];
#pragma unroll
            for (int mi = 0; mi < 2; mi++) {
                int row = warpM * 32 + mi * 16 + (lane & 15);
                uint32_t off = ((uint32_t)(row >> 3) << 10) + ((uint32_t)(row & 7) << 7)
                             + (uint32_t)((s & 3) * 32 + ((lane >> 4) << 4));
                off ^= (off >> 3) & 0x70;
                LDSM_X4(a[mi][0], a[mi][1], a[mi][2], a[mi][3],
                        ab + (uint32_t)(s >> 2) * 8192u + off);
            }
            uint32_t b[2][4];
#pragma unroll
            for (int bt = 0; bt < 2; bt++) {
                int k = s * 16 + (lane & 15);
                uint32_t off = ((uint32_t)(k >> 3) << 10) + ((uint32_t)(k & 7) << 7)
                             + (colbase + (uint32_t)bt * 32 + ((lane >> 4) << 4));
                off ^= (off >> 3) & 0x70;
                LDSM_X4T(b[bt][0], b[bt][1], b[bt][2], b[bt][3], bb + off);
            }
#pragma unroll
            for (int mi = 0; mi < 2; mi++)
#pragma unroll
                for (int nt = 0; nt < 4; nt++)
                    MMA_BF16(acc[mi][nt], a[mi], b[nt >> 1][(nt & 1) * 2],
                             b[nt >> 1][(nt & 1) * 2 + 1]);
        }
    }
}

__device__ __forceinline__ void epi_act64(float (*acc)[4][4], uint8_t* thi, uint8_t* tlo,
                                          const float* bias, int warpM, int warpN, int lane) {
#pragma unroll
    for (int mi = 0; mi < 2; mi++) {
#pragma unroll
        for (int nt = 0; nt < 4; nt++) {
            int r0 = warpM * 32 + mi * 16 + (lane >> 2);
            int n  = warpN * 32 + nt * 8 + (lane & 3) * 2;
            uint32_t slab = (uint32_t)(n >> 6) * 8192u;
            uint32_t kk = (uint32_t)(n & 63);
            float b0v = bias[n], b1v = bias[n + 1];
#pragma unroll
            for (int hh = 0; hh < 2; hh++) {
                int r = r0 + hh * 8;
                float v0 = fmaxf(acc[mi][nt][hh * 2 + 0] + b0v, 0.f);
                float v1 = fmaxf(acc[mi][nt][hh * 2 + 1] + b1v, 0.f);
                __nv_bfloat16 h0 = __float2bfloat16(v0), h1 = __float2bfloat16(v1);
                uint32_t hp = (uint32_t)__bfloat16_as_ushort(h0)
                            | ((uint32_t)__bfloat16_as_ushort(h1) << 16);
                uint32_t lp = pack_bf2(v0 - __bfloat162float(h0), v1 - __bfloat162float(h1));
                uint32_t off = ((uint32_t)(r >> 3) << 10) + ((uint32_t)(r & 7) << 7) + kk * 2;
                off ^= (off >> 3) & 0x70;
                *(uint32_t*)(thi + slab + off) = hp;
                *(uint32_t*)(tlo + slab + off) = lp;
            }
        }
    }
}

// ===========================================================================
__global__ void zero_dh_kernel() {
    size_t i = (size_t)blockIdx.x * blockDim.x + threadIdx.x;
    if (i < (size_t)NND * HH / 4)
        ((float4*)g_dh)[i] = make_float4(0.f, 0.f, 0.f, 0.f);
}

// Edge weights: 8 chunks of 32KB (64k x 128n): W1 c0-3, W2 c4-5, W3 c6-7.
__global__ void prep_w_kernel(const float* __restrict__ W1,
                              const float* __restrict__ W2,
                              const float* __restrict__ W3) {
    int t = blockIdx.x * 256 + threadIdx.x;      // 0..65535
    int ci = t >> 13;       // chunk 0..7
    int e  = t & 8191;
    int n  = e & 127;
    int kl = e >> 7;        // 0..63
    const float* W; int kg;
    if      (ci < 4) { W = W1; kg = ci * 64 + kl; }
    else if (ci < 6) { W = W2; kg = (ci - 4) * 64 + kl; }
    else             { W = W3; kg = (ci - 6) * 64 + kl; }
    float w = W[(size_t)kg * 128 + n];
    __nv_bfloat16 hi = __float2bfloat16(w);
    __nv_bfloat16 lo = __float2bfloat16(w - __bfloat162float(hi));
    uint32_t off = ((uint32_t)(kl >> 3) << 10) + ((uint32_t)(kl & 7) << 7) + (uint32_t)(n & 63) * 2;
    off ^= (off >> 3) & 0x70;
    size_t base = (size_t)ci * 32768 + (size_t)(n >> 6) * 8192 + off;
    *(__nv_bfloat16*)(g_wprep + base) = hi;
    *(__nv_bfloat16*)(g_wprep + base + 16384) = lo;
}

// Node weights: D1 (4 chunks over n), then D2 (4 chunks over k). 64KB/chunk.
__global__ void prep_nw_kernel(const float* __restrict__ D1,
                               const float* __restrict__ D2) {
    int t = blockIdx.x * 256 + threadIdx.x;
    int mat = t >> 16;
    int r   = t & 65535;
    int c   = r >> 14;
    int e   = r & 16383;
    int n   = e & 127;
    int kl  = e >> 7;
    float w;
    if (mat == 0) w = D1[(size_t)kl * FF + c * 128 + n];
    else          w = D2[(size_t)(c * 128 + kl) * HH + n];
    __nv_bfloat16 hi = __float2bfloat16(w);
    __nv_bfloat16 lo = __float2bfloat16(w - __bfloat162float(hi));
    int slab = n >> 6, nn = n & 63;
    uint32_t off = ((uint32_t)(kl >> 3) << 10) + ((uint32_t)(kl & 7) << 7) + nn * 2;
    off ^= (off >> 3) & 0x70;
    size_t base = (size_t)mat * 262144 + (size_t)c * 65536 + (size_t)slab * 16384 + off;
    *(__nv_bfloat16*)(g_nwprep + base) = hi;
    *(__nv_bfloat16*)(g_nwprep + base + 32768) = lo;
}

// SMEM offsets — edge kernel (per-CTA ~98KB → 2 CTAs/SM)
#define OF_SRC  0
#define OF_BIAS 512
#define OF_A    2048           // [hi c0 16K][hi c1 16K][lo c0 16K][lo c1 16K]
#define OF_W    67584          // single 32KB weight chunk buffer
#define SM_EDGE (100352 + 128)

// ===========================================================================
// Edge kernel: fused 3-layer MLP on HMMA (bf16x3), occupancy 2
// ===========================================================================
__global__ __launch_bounds__(256, 2)
void edge_mma_kernel(const float* __restrict__ hE, const int* __restrict__ eidx,
                     const float* __restrict__ b1, const float* __restrict__ b2,
                     const float* __restrict__ b3)
{
    extern __shared__ __align__(16) uint8_t sm8[];
    uint32_t sbr = smem_u32(sm8);
    uint32_t sb  = (sbr + 127u) & ~127u;
    uint8_t* smb = sm8 + (sb - sbr);

    const int tid = threadIdx.x, wid = tid >> 5, lane = tid & 31;
    const int warpM = wid & 3, warpN = wid >> 2;
    const size_t e0 = (size_t)blockIdx.x * TE;

    if (tid < 128) {
        ((int*)(smb + OF_SRC))[tid] = eidx[e0 + tid];       // row 0 = src
        float* bs = (float*)(smb + OF_BIAS);
        bs[tid] = b1[tid]; bs[128 + tid] = b2[tid]; bs[256 + tid] = b3[tid];
    }

    cp_w32(sb + OF_W, g_wprep, tid);                     // W1 c0
    stage_A64(smb, OF_A,         OF_A + 32768, hE, e0, 0,  tid);   // half0
    stage_A64(smb, OF_A + 16384, OF_A + 49152, hE, e0, 64, tid);   // half1
    CP_WAIT(0);
    __syncthreads();

    float acc[2][8][4];
#pragma unroll
    for (int mi = 0; mi < 2; mi++)
#pragma unroll
        for (int nt = 0; nt < 8; nt++)
#pragma unroll
            for (int q = 0; q < 4; q++) acc[mi][nt][q] = 0.f;

    const float* bias_sm = (const float*)(smb + OF_BIAS);

    // ---- layer 1: 4 K-64 chunks ----
    mma_chunk64e(acc, sb + OF_A, sb + OF_A + 32768, sb + OF_W, warpM, warpN, lane);
    __syncthreads();
    cp_w32(sb + OF_W, g_wprep + 32768, tid);             // W1 c1
    CP_WAIT(0);
    __syncthreads();

    mma_chunk64e(acc, sb + OF_A + 16384, sb + OF_A + 49152, sb + OF_W, warpM, warpN, lane);
    __syncthreads();
    cp_w32(sb + OF_W, g_wprep + 65536, tid);             // W1 c2
    stage_A64(smb, OF_A, OF_A + 32768, hE, e0, 128, tid);          // half0 <- k128
    CP_WAIT(0);
    __syncthreads();

    mma_chunk64e(acc, sb + OF_A, sb + OF_A + 32768, sb + OF_W, warpM, warpN, lane);
    __syncthreads();
    cp_w32(sb + OF_W, g_wprep + 98304, tid);             // W1 c3
    stage_A64(smb, OF_A + 16384, OF_A + 49152, hE, e0, 192, tid);  // half1 <- k192
    CP_WAIT(0);
    __syncthreads();

    mma_chunk64e(acc, sb + OF_A + 16384, sb + OF_A + 49152, sb + OF_W, warpM, warpN, lane);
    __syncthreads();

    // epilogue L1 -> M1 over A region; acc zeroed
    epi_acte(acc, smb + OF_A, bias_sm, warpM, warpN, lane);
    cp_w32(sb + OF_W, g_wprep + 131072, tid);            // W2 c0
    CP_WAIT(0);
    __syncthreads();

    // ---- layer 2: 2 K-64 chunks over M1 ----
    mma_chunk64e(acc, sb + OF_A, sb + OF_A + 32768, sb + OF_W, warpM, warpN, lane);
    __syncthreads();
    cp_w32(sb + OF_W, g_wprep + 163840, tid);            // W2 c1
    CP_WAIT(0);
    __syncthreads();
    mma_chunk64e(acc, sb + OF_A + 16384, sb + OF_A + 49152, sb + OF_W, warpM, warpN, lane);
    __syncthreads();

    epi_acte(acc, smb + OF_A, bias_sm + 128, warpM, warpN, lane);
    cp_w32(sb + OF_W, g_wprep + 196608, tid);            // W3 c0
    CP_WAIT(0);
    __syncthreads();

    // ---- layer 3: 2 K-64 chunks over M2 ----
    mma_chunk64e(acc, sb + OF_A, sb + OF_A + 32768, sb + OF_W, warpM, warpN, lane);
    __syncthreads();
    cp_w32(sb + OF_W, g_wprep + 229376, tid);            // W3 c1
    CP_WAIT(0);
    __syncthreads();
    mma_chunk64e(acc, sb + OF_A + 16384, sb + OF_A + 49152, sb + OF_W, warpM, warpN, lane);

    // scatter epilogue: (acc + b3) * SINV -> red.v2 into g_dh[src]
    const int* s_src = (const int*)(smb + OF_SRC);
    const float* b3s = bias_sm + 256;
#pragma unroll
    for (int mi = 0; mi < 2; mi++) {
#pragma unroll
        for (int nt = 0; nt < 8; nt++) {
            int r0 = warpM * 32 + mi * 16 + (lane >> 2);
            int n  = warpN * 64 + nt * 8 + (lane & 3) * 2;
            float bb0 = b3s[n], bb1 = b3s[n + 1];
#pragma unroll
            for (int hh = 0; hh < 2; hh++) {
                int r = r0 + hh * 8;
                int srcn = s_src[r];
                float v0 = (acc[mi][nt][hh * 2 + 0] + bb0) * SINV;
                float v1 = (acc[mi][nt][hh * 2 + 1] + bb1) * SINV;
                float* dst = g_dh + (size_t)srcn * HH + n;
                asm volatile("red.global.add.v2.f32 [%0], {%1, %2};"
                             :: "l"(dst), "f"(v0), "f"(v1) : "memory");
            }
        }
    }
}

// ===========================================================================
// Node kernel on HMMA, M=64 tile (validated round 12, unchanged)
// ===========================================================================
#define N_OF_A    0
#define N_OF_T    32768
#define N_OF_W0   65536
#define N_OF_W1   131072
#define N_OF_Z    131072
#define N_OF_MU   196608
#define N_OF_RS   196864
#define N_OF_DB1  197120
#define N_OF_DB2  199168
#define N_OF_G1   199680
#define N_OF_BE1  200192
#define N_OF_G2   200704
#define N_OF_BE2  201216
#define SM_NODE   (201728 + 128)
#define LDZ 132

__global__ __launch_bounds__(256, 1)
void node_mma64_kernel(const float* __restrict__ hV,
                       const float* __restrict__ db1, const float* __restrict__ db2,
                       const float* __restrict__ g1, const float* __restrict__ be1,
                       const float* __restrict__ g2, const float* __restrict__ be2,
                       float* __restrict__ out)
{
    extern __shared__ __align__(16) uint8_t sm8[];
    uint32_t sbr = smem_u32(sm8);
    uint32_t sb  = (sbr + 127u) & ~127u;
    uint8_t* smb = sm8 + (sb - sbr);

    const int tid = threadIdx.x, wid = tid >> 5, lane = tid & 31;
    const int warpM = wid & 1, warpN = wid >> 1;
    const int n0 = blockIdx.x * 64;
    const int nrem = min(64, NND - n0);

    float* Z    = (float*)(smb + N_OF_Z);
    float* s_mu = (float*)(smb + N_OF_MU);
    float* s_rs = (float*)(smb + N_OF_RS);
    float* db1s = (float*)(smb + N_OF_DB1);
    float* db2s = (float*)(smb + N_OF_DB2);
    float* g1s  = (float*)(smb + N_OF_G1);
    float* be1s = (float*)(smb + N_OF_BE1);
    float* g2s  = (float*)(smb + N_OF_G2);
    float* be2s = (float*)(smb + N_OF_BE2);

    cp_w(sb + N_OF_W0, g_nwprep, tid);

    db1s[tid] = db1[tid]; db1s[256 + tid] = db1[256 + tid];
    if (tid < 128) {
        db2s[tid] = db2[tid];
        g1s[tid] = g1[tid]; be1s[tid] = be1[tid];
        g2s[tid] = g2[tid]; be2s[tid] = be2[tid];
    }

#pragma unroll
    for (int it = 0; it < 32; it++) {
        int idx = tid + 256 * it;
        int r = idx >> 7, c = idx & 127;
        float v = 0.f;
        if (r < nrem) {
            size_t g = (size_t)(n0 + r) * HH + c;
            v = hV[g] + g_dh[g];
        }
        Z[r * LDZ + c] = v;
    }
    __syncthreads();

    if (tid < 64) {
        const float* zr = Z + tid * LDZ;
        float s = 0.f;
        for (int c = 0; c < HH; c++) s += zr[c];
        float mu = s * (1.f / HH);
        float v = 0.f;
        for (int c = 0; c < HH; c++) { float d = zr[c] - mu; v += d * d; }
        s_mu[tid] = mu;
        s_rs[tid] = rsqrtf(v * (1.f / HH) + 1e-5f);
    }
    __syncthreads();

#pragma unroll
    for (int it = 0; it < 16; it++) {
        int idx = tid + 256 * it;
        int r = idx >> 6, c = (idx & 63) * 2;
        float mu = s_mu[r], rs = s_rs[r];
        float v0 = (Z[r * LDZ + c]     - mu) * rs * g1s[c]     + be1s[c];
        float v1 = (Z[r * LDZ + c + 1] - mu) * rs * g1s[c + 1] + be1s[c + 1];
        __nv_bfloat16 h0 = __float2bfloat16(v0), h1 = __float2bfloat16(v1);
        uint32_t hp = (uint32_t)__bfloat16_as_ushort(h0)
                    | ((uint32_t)__bfloat16_as_ushort(h1) << 16);
        uint32_t lp = pack_bf2(v0 - __bfloat162float(h0), v1 - __bfloat162float(h1));
        uint32_t slab = (uint32_t)(c >> 6) * 8192;
        uint32_t kk = (uint32_t)(c & 63);
        uint32_t off = ((uint32_t)(r >> 3) << 10) + ((uint32_t)(r & 7) << 7) + kk * 2;
        off ^= (off >> 3) & 0x70;
        *(uint32_t*)(smb + N_OF_A + slab + off) = hp;
        *(uint32_t*)(smb + N_OF_A + 16384 + slab + off) = lp;
    }
    __syncthreads();

    float acc2[2][4][4];
#pragma unroll
    for (int mi = 0; mi < 2; mi++)
#pragma unroll
        for (int nt = 0; nt < 4; nt++)
#pragma unroll
            for (int q = 0; q < 4; q++) acc2[mi][nt][q] = 0.f;

    for (int qc = 0; qc < 4; qc++) {
        cp_w(sb + N_OF_W1, g_nwprep + 262144 + (size_t)qc * 65536, tid);
        CP_WAIT(1);
        __syncthreads();

        float acc1[2][4][4];
#pragma unroll
        for (int mi = 0; mi < 2; mi++)
#pragma unroll
            for (int nt = 0; nt < 4; nt++)
#pragma unroll
                for (int q = 0; q < 4; q++) acc1[mi][nt][q] = 0.f;

        mma_chunk64(acc1, sb + N_OF_A, sb + N_OF_A + 16384, sb + N_OF_W0,
                    warpM, warpN, lane);
        __syncthreads();

        epi_act64(acc1, smb + N_OF_T, smb + N_OF_T + 16384, db1s + qc * 128,
                  warpM, warpN, lane);
        if (qc < 3) {
            cp_w(sb + N_OF_W0, g_nwprep + (size_t)(qc + 1) * 65536, tid);
            CP_WAIT(1);
        } else {
            CP_WAIT(0);
        }
        __syncthreads();

        mma_chunk64(acc2, sb + N_OF_T, sb + N_OF_T + 16384, sb + N_OF_W1,
                    warpM, warpN, lane);
        __syncthreads();
    }

#pragma unroll
    for (int mi = 0; mi < 2; mi++) {
#pragma unroll
        for (int nt = 0; nt < 4; nt++) {
            int r0 = warpM * 32 + mi * 16 + (lane >> 2);
            int n  = warpN * 32 + nt * 8 + (lane & 3) * 2;
            float bb0 = db2s[n], bb1 = db2s[n + 1];
            uint32_t slab = (uint32_t)(n >> 6) * 8192;
            uint32_t kk = (uint32_t)(n & 63);
#pragma unroll
            for (int hh = 0; hh < 2; hh++) {
                int r = r0 + hh * 8;
                uint32_t off = ((uint32_t)(r >> 3) << 10) + ((uint32_t)(r & 7) << 7) + kk * 2;
                off ^= (off >> 3) & 0x70;
                uint32_t hp = *(uint32_t*)(smb + N_OF_A + slab + off);
                uint32_t lp = *(uint32_t*)(smb + N_OF_A + 16384 + slab + off);
                float h0 = __bfloat162float(__ushort_as_bfloat16((unsigned short)(hp & 0xFFFF)))
                         + __bfloat162float(__ushort_as_bfloat16((unsigned short)(lp & 0xFFFF)));
                float h1 = __bfloat162float(__ushort_as_bfloat16((unsigned short)(hp >> 16)))
                         + __bfloat162float(__ushort_as_bfloat16((unsigned short)(lp >> 16)));
                Z[r * LDZ + n]     = h0 + acc2[mi][nt][hh * 2 + 0] + bb0;
                Z[r * LDZ + n + 1] = h1 + acc2[mi][nt][hh * 2 + 1] + bb1;
            }
        }
    }
    __syncthreads();

    if (tid < 64) {
        const float* zr = Z + tid * LDZ;
        float s = 0.f;
        for (int c = 0; c < HH; c++) s += zr[c];
        float mu = s * (1.f / HH);
        float v = 0.f;
        for (int c = 0; c < HH; c++) { float d = zr[c] - mu; v += d * d; }
        s_mu[tid] = mu;
        s_rs[tid] = rsqrtf(v * (1.f / HH) + 1e-5f);
    }
    __syncthreads();

#pragma unroll
    for (int it = 0; it < 32; it++) {
        int idx = tid + 256 * it;
        int r = idx >> 7, c = idx & 127;
        if (r < nrem)
            out[(size_t)(n0 + r) * HH + c] =
                (Z[r * LDZ + c] - s_mu[r]) * s_rs[r] * g2s[c] + be2s[c];
    }
}

// ===========================================================================
extern "C" void kernel_launch(void* const* d_in, const int* in_sizes, int n_in,
                              void* d_out, int out_size)
{
    const float* hV   = (const float*)d_in[0];
    const float* hE   = (const float*)d_in[1];
    const int*   eidx = (const int*)d_in[2];   // int32 [2, NE]; row 0 = src
    const float* W1  = (const float*)d_in[3];
    const float* b1  = (const float*)d_in[4];
    const float* W2  = (const float*)d_in[5];
    const float* b2  = (const float*)d_in[6];
    const float* W3  = (const float*)d_in[7];
    const float* b3  = (const float*)d_in[8];
    const float* D1  = (const float*)d_in[9];
    const float* db1 = (const float*)d_in[10];
    const float* D2  = (const float*)d_in[11];
    const float* db2 = (const float*)d_in[12];
    const float* g1  = (const float*)d_in[13];
    const float* be1 = (const float*)d_in[14];
    const float* g2  = (const float*)d_in[15];
    const float* be2 = (const float*)d_in[16];
    float* out = (float*)d_out;

    cudaFuncSetAttribute(edge_mma_kernel, cudaFuncAttributeMaxDynamicSharedMemorySize,
                         SM_EDGE);
    cudaFuncSetAttribute(node_mma64_kernel, cudaFuncAttributeMaxDynamicSharedMemorySize,
                         SM_NODE);

    zero_dh_kernel<<<(NND * HH / 4 + 255) / 256, 256>>>();
    prep_w_kernel<<<256, 256>>>(W1, W2, W3);
    prep_nw_kernel<<<512, 256>>>(D1, D2);
    edge_mma_kernel<<<NE / TE, 256, SM_EDGE>>>(hE, eidx, b1, b2, b3);
    node_mma64_kernel<<<(NND + 63) / 64, 256, SM_NODE>>>(hV, db1, db2,
                                                         g1, be1, g2, be2, out);
}

// round 15
// speedup vs baseline: 1.3784x; 1.3784x over previous
#include <cuda_runtime.h>
#include <cuda_fp16.h>
#include <stdint.h>
#include <math.h>

#define NE   800000
#define NND  100000
#define HH   128
#define KIN  256
#define FF   512
#define TE   128
#define SINV (1.0f/30.0f)

// scratch: aggregated messages (51.2 MB) + prepped fp16 split weights
__device__ float g_dh[(size_t)NND * HH];
__device__ __align__(16) unsigned char g_wprep[4 * 65536];    // edge W1(2),W2,W3
__device__ __align__(16) unsigned char g_nwprep[8 * 65536];   // node D1(4) + D2(4)

// ===========================================================================
// helpers
// ===========================================================================
__device__ __forceinline__ uint32_t smem_u32(const void* p) {
    uint32_t a;
    asm("{ .reg .u64 t; cvta.to.shared.u64 t, %1; cvt.u32.u64 %0, t; }"
        : "=r"(a) : "l"(p));
    return a;
}

#define LDSM_X4(r0, r1, r2, r3, addr) \
    asm volatile("ldmatrix.sync.aligned.m8n8.x4.shared.b16 {%0,%1,%2,%3}, [%4];" \
        : "=r"(r0), "=r"(r1), "=r"(r2), "=r"(r3) : "r"(addr))

#define LDSM_X4T(r0, r1, r2, r3, addr) \
    asm volatile("ldmatrix.sync.aligned.m8n8.x4.trans.shared.b16 {%0,%1,%2,%3}, [%4];" \
        : "=r"(r0), "=r"(r1), "=r"(r2), "=r"(r3) : "r"(addr))

#define MMA_FP16(d, a, b0, b1) \
    asm volatile("mma.sync.aligned.m16n8k16.row.col.f32.f16.f16.f32 " \
        "{%0,%1,%2,%3}, {%4,%5,%6,%7}, {%8,%9}, {%0,%1,%2,%3};" \
        : "+f"((d)[0]), "+f"((d)[1]), "+f"((d)[2]), "+f"((d)[3]) \
        : "r"((a)[0]), "r"((a)[1]), "r"((a)[2]), "r"((a)[3]), "r"(b0), "r"(b1))

#define CP_WAIT(n) asm volatile("cp.async.wait_group %0;" :: "n"(n) : "memory")

// copy one 64KB weight chunk to SMEM (per-thread 16 x 16B) + commit group
__device__ __forceinline__ void cp_w(uint32_t dsts, const unsigned char* src, int tid) {
#pragma unroll
    for (int i = 0; i < 16; i++) {
        uint32_t o = (uint32_t)(tid + 256 * i) * 16u;
        asm volatile("cp.async.cg.shared.global [%0], [%1], 16;"
                     :: "r"(dsts + o), "l"(src + o) : "memory");
    }
    asm volatile("cp.async.commit_group;" ::: "memory");
}

__device__ __forceinline__ uint32_t pack_hf2(float v0, float v1) {
    __half h0 = __float2half(v0), h1 = __float2half(v1);
    return (uint32_t)__half_as_ushort(h0) | ((uint32_t)__half_as_ushort(h1) << 16);
}

// ===========================================================================
// EDGE machinery — 128x128 tile, warps 4x2, K=128 chunks, fp16 2-pass
// A slab (hi only): 2 x 16KB (k0-63, k64-127).
// W chunk 64KB: [hi n0-63 16K][hi n64-127 16K][lo n0-63][lo n64-127]
// ===========================================================================
__device__ __forceinline__ void mma_chunk(float (*acc)[8][4], uint32_t ab,
                                          uint32_t wb, int warpM, int warpN, int lane) {
#pragma unroll
    for (int s = 0; s < 8; s++) {
        uint32_t a[2][4];
#pragma unroll
        for (int mi = 0; mi < 2; mi++) {
            int row = warpM * 32 + mi * 16 + (lane & 15);
            uint32_t off = ((uint32_t)(row >> 3) << 10) + ((uint32_t)(row & 7) << 7)
                         + (uint32_t)((s & 3) * 32 + ((lane >> 4) << 4));
            off ^= (off >> 3) & 0x70;
            LDSM_X4(a[mi][0], a[mi][1], a[mi][2], a[mi][3],
                    ab + (uint32_t)(s >> 2) * 16384u + off);
        }
        int k = s * 16 + (lane & 15);
        uint32_t koff = ((uint32_t)(k >> 3) << 10) + ((uint32_t)(k & 7) << 7)
                      + ((uint32_t)(lane >> 4) << 4);
#pragma unroll
        for (int pass = 0; pass < 2; pass++) {
            uint32_t bb = wb + (uint32_t)pass * 32768u + (uint32_t)warpN * 16384u;
            uint32_t b[4][4];
#pragma unroll
            for (int bt = 0; bt < 4; bt++) {
                uint32_t off = koff + (uint32_t)bt * 32u;
                off ^= (off >> 3) & 0x70;
                LDSM_X4T(b[bt][0], b[bt][1], b[bt][2], b[bt][3], bb + off);
            }
#pragma unroll
            for (int mi = 0; mi < 2; mi++)
#pragma unroll
                for (int nt = 0; nt < 8; nt++)
                    MMA_FP16(acc[mi][nt], a[mi], b[nt >> 1][(nt & 1) * 2],
                             b[nt >> 1][(nt & 1) * 2 + 1]);
        }
    }
}

// edge layer epilogue: relu(acc+bias) -> fp16 -> A slabs (hi only). Zeros acc.
__device__ __forceinline__ void epi_act(float (*acc)[8][4], uint8_t* abase,
                                        const float* bias, int warpM, int warpN, int lane) {
    uint32_t slab = (uint32_t)warpN * 16384u;
#pragma unroll
    for (int mi = 0; mi < 2; mi++) {
#pragma unroll
        for (int nt = 0; nt < 8; nt++) {
            int r0 = warpM * 32 + mi * 16 + (lane >> 2);
            int kk = nt * 8 + (lane & 3) * 2;
            int n  = warpN * 64 + kk;
            float b0v = bias[n], b1v = bias[n + 1];
#pragma unroll
            for (int hh = 0; hh < 2; hh++) {
                int r = r0 + hh * 8;
                float v0 = fmaxf(acc[mi][nt][hh * 2 + 0] + b0v, 0.f);
                float v1 = fmaxf(acc[mi][nt][hh * 2 + 1] + b1v, 0.f);
                uint32_t off = ((uint32_t)(r >> 3) << 10) + ((uint32_t)(r & 7) << 7)
                             + (uint32_t)kk * 2;
                off ^= (off >> 3) & 0x70;
                *(uint32_t*)(abase + slab + off) = pack_hf2(v0, v1);
            }
            acc[mi][nt][0] = 0.f; acc[mi][nt][1] = 0.f;
            acc[mi][nt][2] = 0.f; acc[mi][nt][3] = 0.f;
        }
    }
}

// Stage a K=128 edge activation chunk: fp32 -> fp16 (hi only) into SW128 slabs.
__device__ __forceinline__ void stage_A(uint8_t* smb, uint32_t of_a,
                                        const float* __restrict__ hE,
                                        size_t e0, int kc, int tid) {
#pragma unroll
    for (int it = 0; it < 16; it++) {
        int idx = tid + 256 * it;           // 0..4095 (128 rows x 32 float4)
        int r = idx >> 5, c4 = idx & 31;
        float4 v = *(const float4*)(hE + (e0 + r) * KIN + kc + c4 * 4);
        uint32_t hA = pack_hf2(v.x, v.y);
        uint32_t hB = pack_hf2(v.z, v.w);
        uint32_t off = ((uint32_t)(r >> 3) << 10) + ((uint32_t)(r & 7) << 7)
                     + ((uint32_t)(c4 & 15) << 3);
        off ^= (off >> 3) & 0x70;
        uint32_t slab = (uint32_t)(c4 >> 4) * 16384;
        *(uint2*)(smb + of_a + slab + off) = make_uint2(hA, hB);
    }
}

// ===========================================================================
// NODE machinery — 64x128 tile, warps 2x4 (warp tile 32x32), fp16 2-pass
// A hi slabs: 2 x 8KB; A lo (residual only) at +16384. T hi: 2 x 8KB.
// ===========================================================================
__device__ __forceinline__ void mma_chunk64(float (*acc)[4][4], uint32_t ab,
                                            uint32_t wb, int warpM, int warpN, int lane) {
    const uint32_t colbase = (uint32_t)(warpN & 1) * 64u;
    const uint32_t wslab   = (uint32_t)(warpN >> 1) * 16384u;
#pragma unroll
    for (int s = 0; s < 8; s++) {
        uint32_t a[2][4];
#pragma unroll
        for (int mi = 0; mi < 2; mi++) {
            int row = warpM * 32 + mi * 16 + (lane & 15);
            uint32_t off = ((uint32_t)(row >> 3) << 10) + ((uint32_t)(row & 7) << 7)
                         + (uint32_t)((s & 3) * 32 + ((lane >> 4) << 4));
            off ^= (off >> 3) & 0x70;
            LDSM_X4(a[mi][0], a[mi][1], a[mi][2], a[mi][3],
                    ab + (uint32_t)(s >> 2) * 8192u + off);
        }
        int k = s * 16 + (lane & 15);
        uint32_t koff = ((uint32_t)(k >> 3) << 10) + ((uint32_t)(k & 7) << 7)
                      + ((uint32_t)(lane >> 4) << 4);
#pragma unroll
        for (int pass = 0; pass < 2; pass++) {
            uint32_t bb = wb + (uint32_t)pass * 32768u + wslab;
            uint32_t b[2][4];
#pragma unroll
            for (int bt = 0; bt < 2; bt++) {
                uint32_t off = koff + colbase + (uint32_t)bt * 32u;
                off ^= (off >> 3) & 0x70;
                LDSM_X4T(b[bt][0], b[bt][1], b[bt][2], b[bt][3], bb + off);
            }
#pragma unroll
            for (int mi = 0; mi < 2; mi++)
#pragma unroll
                for (int nt = 0; nt < 4; nt++)
                    MMA_FP16(acc[mi][nt], a[mi], b[nt >> 1][(nt & 1) * 2],
                             b[nt >> 1][(nt & 1) * 2 + 1]);
        }
    }
}

// node FFN epilogue: relu(acc+bias) -> fp16 -> T hi slabs
__device__ __forceinline__ void epi_act64(float (*acc)[4][4], uint8_t* thi,
                                          const float* bias, int warpM, int warpN, int lane) {
#pragma unroll
    for (int mi = 0; mi < 2; mi++) {
#pragma unroll
        for (int nt = 0; nt < 4; nt++) {
            int r0 = warpM * 32 + mi * 16 + (lane >> 2);
            int n  = warpN * 32 + nt * 8 + (lane & 3) * 2;
            uint32_t slab = (uint32_t)(n >> 6) * 8192u;
            uint32_t kk = (uint32_t)(n & 63);
            float b0v = bias[n], b1v = bias[n + 1];
#pragma unroll
            for (int hh = 0; hh < 2; hh++) {
                int r = r0 + hh * 8;
                float v0 = fmaxf(acc[mi][nt][hh * 2 + 0] + b0v, 0.f);
                float v1 = fmaxf(acc[mi][nt][hh * 2 + 1] + b1v, 0.f);
                uint32_t off = ((uint32_t)(r >> 3) << 10) + ((uint32_t)(r & 7) << 7) + kk * 2;
                off ^= (off >> 3) & 0x70;
                *(uint32_t*)(thi + slab + off) = pack_hf2(v0, v1);
            }
        }
    }
}

// ===========================================================================
__global__ void zero_dh_kernel() {
    size_t i = (size_t)blockIdx.x * blockDim.x + threadIdx.x;
    if (i < (size_t)NND * HH / 4)
        ((float4*)g_dh)[i] = make_float4(0.f, 0.f, 0.f, 0.f);
}

// Edge weights: fp16 hi/lo [k][n] slabs, SW128 swizzled.
// Chunks: 0=W1[k0:128), 1=W1[k128:256), 2=W2, 3=W3. 64KB/chunk.
__global__ void prep_w_kernel(const float* __restrict__ W1,
                              const float* __restrict__ W2,
                              const float* __restrict__ W3) {
    int t = blockIdx.x * 256 + threadIdx.x;      // 0..65535
    int c  = t >> 14;
    int r  = t & 16383;
    int n  = r & 127;
    int kl = r >> 7;
    const float* W; int kg;
    if      (c == 0) { W = W1; kg = kl; }
    else if (c == 1) { W = W1; kg = kl + 128; }
    else if (c == 2) { W = W2; kg = kl; }
    else             { W = W3; kg = kl; }
    float w = W[(size_t)kg * 128 + n];
    __half hi = __float2half(w);
    __half lo = __float2half(w - __half2float(hi));
    int slab = n >> 6, nn = n & 63;
    uint32_t off = ((uint32_t)(kl >> 3) << 10) + ((uint32_t)(kl & 7) << 7) + nn * 2;
    off ^= (off >> 3) & 0x70;
    size_t base = (size_t)c * 65536 + (size_t)slab * 16384 + off;
    *(__half*)(g_wprep + base) = hi;
    *(__half*)(g_wprep + base + 32768) = lo;
}

// Node weights: D1 (4 chunks over n), then D2 (4 chunks over k). 64KB/chunk.
__global__ void prep_nw_kernel(const float* __restrict__ D1,
                               const float* __restrict__ D2) {
    int t = blockIdx.x * 256 + threadIdx.x;      // 0..131071
    int mat = t >> 16;
    int r   = t & 65535;
    int c   = r >> 14;
    int e   = r & 16383;
    int n   = e & 127;
    int kl  = e >> 7;
    float w;
    if (mat == 0) w = D1[(size_t)kl * FF + c * 128 + n];
    else          w = D2[(size_t)(c * 128 + kl) * HH + n];
    __half hi = __float2half(w);
    __half lo = __float2half(w - __half2float(hi));
    int slab = n >> 6, nn = n & 63;
    uint32_t off = ((uint32_t)(kl >> 3) << 10) + ((uint32_t)(kl & 7) << 7) + nn * 2;
    off ^= (off >> 3) & 0x70;
    size_t base = (size_t)mat * 262144 + (size_t)c * 65536 + (size_t)slab * 16384 + off;
    *(__half*)(g_nwprep + base) = hi;
    *(__half*)(g_nwprep + base + 32768) = lo;
}

// SMEM offsets — edge kernel (~163KB/CTA, occ 1)
#define OF_SRC  0
#define OF_BIAS 512
#define OF_A    2048           // hi only: [slab0 16K][slab1 16K]
#define OF_W0   34816
#define OF_W1   100352
#define SM_EDGE (165888 + 128)

// ===========================================================================
// Edge kernel: fused 3-layer MLP on HMMA (fp16 2-pass) + red scatter
// ===========================================================================
__global__ __launch_bounds__(256, 1)
void edge_mma_kernel(const float* __restrict__ hE, const int* __restrict__ eidx,
                     const float* __restrict__ b1, const float* __restrict__ b2,
                     const float* __restrict__ b3)
{
    extern __shared__ __align__(16) uint8_t sm8[];
    uint32_t sbr = smem_u32(sm8);
    uint32_t sb  = (sbr + 127u) & ~127u;
    uint8_t* smb = sm8 + (sb - sbr);

    const int tid = threadIdx.x, wid = tid >> 5, lane = tid & 31;
    const int warpM = wid & 3, warpN = wid >> 2;
    const size_t e0 = (size_t)blockIdx.x * TE;

    if (tid < 128) {
        ((int*)(smb + OF_SRC))[tid] = eidx[e0 + tid];       // row 0 = src
        float* bs = (float*)(smb + OF_BIAS);
        bs[tid] = b1[tid]; bs[128 + tid] = b2[tid]; bs[256 + tid] = b3[tid];
    }

    cp_w(sb + OF_W0, g_wprep, tid);              // G0: W1 chunk k0-127
    cp_w(sb + OF_W1, g_wprep + 65536, tid);      // G1: W1 chunk k128-255

    stage_A(smb, OF_A, hE, e0, 0, tid);
    CP_WAIT(1);
    __syncthreads();

    float acc[2][8][4];
#pragma unroll
    for (int mi = 0; mi < 2; mi++)
#pragma unroll
        for (int nt = 0; nt < 8; nt++)
#pragma unroll
            for (int q = 0; q < 4; q++) acc[mi][nt][q] = 0.f;

    const float* bias_sm = (const float*)(smb + OF_BIAS);

    // ---- layer 1, chunk 0 ----
    mma_chunk(acc, sb + OF_A, sb + OF_W0, warpM, warpN, lane);
    __syncthreads();

    // ---- layer 1, chunk 1 ----
    cp_w(sb + OF_W0, g_wprep + 131072, tid);     // G2: W2 into buf0
    stage_A(smb, OF_A, hE, e0, 128, tid);
    CP_WAIT(1);                                  // G1 done (G2 may pend)
    __syncthreads();
    mma_chunk(acc, sb + OF_A, sb + OF_W1, warpM, warpN, lane);
    __syncthreads();

    epi_act(acc, smb + OF_A, bias_sm, warpM, warpN, lane);
    cp_w(sb + OF_W1, g_wprep + 196608, tid);     // G3: W3 into buf1
    CP_WAIT(1);                                  // G2 done
    __syncthreads();

    // ---- layer 2 ----
    mma_chunk(acc, sb + OF_A, sb + OF_W0, warpM, warpN, lane);
    __syncthreads();
    epi_act(acc, smb + OF_A, bias_sm + 128, warpM, warpN, lane);
    CP_WAIT(0);                                  // G3 done
    __syncthreads();

    // ---- layer 3 ----
    mma_chunk(acc, sb + OF_A, sb + OF_W1, warpM, warpN, lane);

    // scatter epilogue: (acc + b3) * SINV -> red.v2 into g_dh[src]
    const int* s_src = (const int*)(smb + OF_SRC);
    const float* b3s = bias_sm + 256;
#pragma unroll
    for (int mi = 0; mi < 2; mi++) {
#pragma unroll
        for (int nt = 0; nt < 8; nt++) {
            int r0 = warpM * 32 + mi * 16 + (lane >> 2);
            int n  = warpN * 64 + nt * 8 + (lane & 3) * 2;
            float bb0 = b3s[n], bb1 = b3s[n + 1];
#pragma unroll
            for (int hh = 0; hh < 2; hh++) {
                int r = r0 + hh * 8;
                int srcn = s_src[r];
                float v0 = (acc[mi][nt][hh * 2 + 0] + bb0) * SINV;
                float v1 = (acc[mi][nt][hh * 2 + 1] + bb1) * SINV;
                float* dst = g_dh + (size_t)srcn * HH + n;
                asm volatile("red.global.add.v2.f32 [%0], {%1, %2};"
                             :: "l"(dst), "f"(v0), "f"(v1) : "memory");
            }
        }
    }
}

// ===========================================================================
// Node kernel on HMMA, M=64 tile, fp16 2-pass
// ===========================================================================
#define N_OF_A    0            // A hi 16K (2x8K slabs); A lo (residual) at +16384
#define N_OF_T    32768        // T hi 16K (2x8K slabs)
#define N_OF_W0   49152        // 64K: D1 chunks
#define N_OF_W1   114688       // 64K: D2 chunks; Z overlays (dead phases)
#define N_OF_Z    114688       // fp32 [64][132] = 33792
#define N_OF_MU   180224
#define N_OF_RS   180480
#define N_OF_DB1  180736       // 512 floats
#define N_OF_DB2  182784
#define N_OF_G1   183296
#define N_OF_BE1  183808
#define N_OF_G2   184320
#define N_OF_BE2  184832
#define SM_NODE   (185344 + 128)
#define LDZ 132

__global__ __launch_bounds__(256, 1)
void node_mma64_kernel(const float* __restrict__ hV,
                       const float* __restrict__ db1, const float* __restrict__ db2,
                       const float* __restrict__ g1, const float* __restrict__ be1,
                       const float* __restrict__ g2, const float* __restrict__ be2,
                       float* __restrict__ out)
{
    extern __shared__ __align__(16) uint8_t sm8[];
    uint32_t sbr = smem_u32(sm8);
    uint32_t sb  = (sbr + 127u) & ~127u;
    uint8_t* smb = sm8 + (sb - sbr);

    const int tid = threadIdx.x, wid = tid >> 5, lane = tid & 31;
    const int warpM = wid & 1, warpN = wid >> 1;     // 2 x 4 warp grid
    const int n0 = blockIdx.x * 64;
    const int nrem = min(64, NND - n0);

    float* Z    = (float*)(smb + N_OF_Z);
    float* s_mu = (float*)(smb + N_OF_MU);
    float* s_rs = (float*)(smb + N_OF_RS);
    float* db1s = (float*)(smb + N_OF_DB1);
    float* db2s = (float*)(smb + N_OF_DB2);
    float* g1s  = (float*)(smb + N_OF_G1);
    float* be1s = (float*)(smb + N_OF_BE1);
    float* g2s  = (float*)(smb + N_OF_G2);
    float* be2s = (float*)(smb + N_OF_BE2);

    cp_w(sb + N_OF_W0, g_nwprep, tid);               // G0: D1 c0

    db1s[tid] = db1[tid]; db1s[256 + tid] = db1[256 + tid];
    if (tid < 128) {
        db2s[tid] = db2[tid];
        g1s[tid] = g1[tid]; be1s[tid] = be1[tid];
        g2s[tid] = g2[tid]; be2s[tid] = be2[tid];
    }

    // phase 1: Z = hV + dh  (64 rows)
#pragma unroll
    for (int it = 0; it < 32; it++) {
        int idx = tid + 256 * it;
        int r = idx >> 7, c = idx & 127;
        float v = 0.f;
        if (r < nrem) {
            size_t g = (size_t)(n0 + r) * HH + c;
            v = hV[g] + g_dh[g];
        }
        Z[r * LDZ + c] = v;
    }
    __syncthreads();

    // LN1 row stats
    if (tid < 64) {
        const float* zr = Z + tid * LDZ;
        float s = 0.f;
        for (int c = 0; c < HH; c++) s += zr[c];
        float mu = s * (1.f / HH);
        float v = 0.f;
        for (int c = 0; c < HH; c++) { float d = zr[c] - mu; v += d * d; }
        s_mu[tid] = mu;
        s_rs[tid] = rsqrtf(v * (1.f / HH) + 1e-5f);
    }
    __syncthreads();

    // h = LN1(z) -> A hi slabs (MMA) + lo slabs (exact residual)
#pragma unroll
    for (int it = 0; it < 16; it++) {
        int idx = tid + 256 * it;        // 0..4095 pairs
        int r = idx >> 6, c = (idx & 63) * 2;
        float mu = s_mu[r], rs = s_rs[r];
        float v0 = (Z[r * LDZ + c]     - mu) * rs * g1s[c]     + be1s[c];
        float v1 = (Z[r * LDZ + c + 1] - mu) * rs * g1s[c + 1] + be1s[c + 1];
        __half h0 = __float2half(v0), h1 = __float2half(v1);
        uint32_t hp = (uint32_t)__half_as_ushort(h0)
                    | ((uint32_t)__half_as_ushort(h1) << 16);
        uint32_t lp = pack_hf2(v0 - __half2float(h0), v1 - __half2float(h1));
        uint32_t slab = (uint32_t)(c >> 6) * 8192;
        uint32_t kk = (uint32_t)(c & 63);
        uint32_t off = ((uint32_t)(r >> 3) << 10) + ((uint32_t)(r & 7) << 7) + kk * 2;
        off ^= (off >> 3) & 0x70;
        *(uint32_t*)(smb + N_OF_A + slab + off) = hp;
        *(uint32_t*)(smb + N_OF_A + 16384 + slab + off) = lp;
    }
    __syncthreads();     // Z dead; W1 region may now be written

    float acc2[2][4][4];
#pragma unroll
    for (int mi = 0; mi < 2; mi++)
#pragma unroll
        for (int nt = 0; nt < 4; nt++)
#pragma unroll
            for (int q = 0; q < 4; q++) acc2[mi][nt][q] = 0.f;

    // FFN: 4 q-chunks of 128, double-buffered weights (W0=D1, W1=D2)
    for (int qc = 0; qc < 4; qc++) {
        cp_w(sb + N_OF_W1, g_nwprep + 262144 + (size_t)qc * 65536, tid);  // D2[qc]
        CP_WAIT(1);                      // D1[qc] in W0 ready
        __syncthreads();

        float acc1[2][4][4];
#pragma unroll
        for (int mi = 0; mi < 2; mi++)
#pragma unroll
            for (int nt = 0; nt < 4; nt++)
#pragma unroll
                for (int q = 0; q < 4; q++) acc1[mi][nt][q] = 0.f;

        mma_chunk64(acc1, sb + N_OF_A, sb + N_OF_W0, warpM, warpN, lane);
        __syncthreads();                 // W0 reads done before refill

        epi_act64(acc1, smb + N_OF_T, db1s + qc * 128, warpM, warpN, lane);
        if (qc < 3) {
            cp_w(sb + N_OF_W0, g_nwprep + (size_t)(qc + 1) * 65536, tid);  // D1[qc+1]
            CP_WAIT(1);                  // D2[qc] in W1 ready
        } else {
            CP_WAIT(0);
        }
        __syncthreads();                 // T visible + W1 ready

        mma_chunk64(acc2, sb + N_OF_T, sb + N_OF_W1, warpM, warpN, lane);
        __syncthreads();                 // W1 reads done before next D2 copy
    }

    // y = h + dh2 + db2 -> Z (W1 region dead again); h exact from hi+lo
#pragma unroll
    for (int mi = 0; mi < 2; mi++) {
#pragma unroll
        for (int nt = 0; nt < 4; nt++) {
            int r0 = warpM * 32 + mi * 16 + (lane >> 2);
            int n  = warpN * 32 + nt * 8 + (lane & 3) * 2;
            float bb0 = db2s[n], bb1 = db2s[n + 1];
            uint32_t slab = (uint32_t)(n >> 6) * 8192;
            uint32_t kk = (uint32_t)(n & 63);
#pragma unroll
            for (int hh = 0; hh < 2; hh++) {
                int r = r0 + hh * 8;
                uint32_t off = ((uint32_t)(r >> 3) << 10) + ((uint32_t)(r & 7) << 7) + kk * 2;
                off ^= (off >> 3) & 0x70;
                uint32_t hp = *(uint32_t*)(smb + N_OF_A + slab + off);
                uint32_t lp = *(uint32_t*)(smb + N_OF_A + 16384 + slab + off);
                float h0 = __half2float(__ushort_as_half((unsigned short)(hp & 0xFFFF)))
                         + __half2float(__ushort_as_half((unsigned short)(lp & 0xFFFF)));
                float h1 = __half2float(__ushort_as_half((unsigned short)(hp >> 16)))
                         + __half2float(__ushort_as_half((unsigned short)(lp >> 16)));
                Z[r * LDZ + n]     = h0 + acc2[mi][nt][hh * 2 + 0] + bb0;
                Z[r * LDZ + n + 1] = h1 + acc2[mi][nt][hh * 2 + 1] + bb1;
            }
        }
    }
    __syncthreads();

    // LN2 row stats
    if (tid < 64) {
        const float* zr = Z + tid * LDZ;
        float s = 0.f;
        for (int c = 0; c < HH; c++) s += zr[c];
        float mu = s * (1.f / HH);
        float v = 0.f;
        for (int c = 0; c < HH; c++) { float d = zr[c] - mu; v += d * d; }
        s_mu[tid] = mu;
        s_rs[tid] = rsqrtf(v * (1.f / HH) + 1e-5f);
    }
    __syncthreads();

#pragma unroll
    for (int it = 0; it < 32; it++) {
        int idx = tid + 256 * it;
        int r = idx >> 7, c = idx & 127;
        if (r < nrem)
            out[(size_t)(n0 + r) * HH + c] =
                (Z[r * LDZ + c] - s_mu[r]) * s_rs[r] * g2s[c] + be2s[c];
    }
}

// ===========================================================================
extern "C" void kernel_launch(void* const* d_in, const int* in_sizes, int n_in,
                              void* d_out, int out_size)
{
    const float* hV   = (const float*)d_in[0];
    const float* hE   = (const float*)d_in[1];
    const int*   eidx = (const int*)d_in[2];   // int32 [2, NE]; row 0 = src
    const float* W1  = (const float*)d_in[3];
    const float* b1  = (const float*)d_in[4];
    const float* W2  = (const float*)d_in[5];
    const float* b2  = (const float*)d_in[6];
    const float* W3  = (const float*)d_in[7];
    const float* b3  = (const float*)d_in[8];
    const float* D1  = (const float*)d_in[9];
    const float* db1 = (const float*)d_in[10];
    const float* D2  = (const float*)d_in[11];
    const float* db2 = (const float*)d_in[12];
    const float* g1  = (const float*)d_in[13];
    const float* be1 = (const float*)d_in[14];
    const float* g2  = (const float*)d_in[15];
    const float* be2 = (const float*)d_in[16];
    float* out = (float*)d_out;

    cudaFuncSetAttribute(edge_mma_kernel, cudaFuncAttributeMaxDynamicSharedMemorySize,
                         SM_EDGE);
    cudaFuncSetAttribute(node_mma64_kernel, cudaFuncAttributeMaxDynamicSharedMemorySize,
                         SM_NODE);

    zero_dh_kernel<<<(NND * HH / 4 + 255) / 256, 256>>>();
    prep_w_kernel<<<256, 256>>>(W1, W2, W3);
    prep_nw_kernel<<<512, 256>>>(D1, D2);
    edge_mma_kernel<<<NE / TE, 256, SM_EDGE>>>(hE, eidx, b1, b2, b3);
    node_mma64_kernel<<<(NND + 63) / 64, 256, SM_NODE>>>(hV, db1, db2,
                                                         g1, be1, g2, be2, out);
}

// round 16
// speedup vs baseline: 2.1285x; 1.5442x over previous
#include <cuda_runtime.h>
#include <cuda_fp16.h>
#include <stdint.h>
#include <math.h>

#define NE   800000
#define NND  100000
#define HH   128
#define KIN  256
#define FF   512
#define TE   128
#define SINV (1.0f/30.0f)

// scratch: aggregated messages (51.2 MB) + prepped fp16 split weights
__device__ float g_dh[(size_t)NND * HH];
__device__ __align__(16) unsigned char g_wprep[4 * 65536];    // edge W1(2),W2,W3
__device__ __align__(16) unsigned char g_nwprep[8 * 65536];   // node D1(4) + D2(4)

// ===========================================================================
// helpers
// ===========================================================================
__device__ __forceinline__ uint32_t smem_u32(const void* p) {
    uint32_t a;
    asm("{ .reg .u64 t; cvta.to.shared.u64 t, %1; cvt.u32.u64 %0, t; }"
        : "=r"(a) : "l"(p));
    return a;
}

#define LDSM_X4(r0, r1, r2, r3, addr) \
    asm volatile("ldmatrix.sync.aligned.m8n8.x4.shared.b16 {%0,%1,%2,%3}, [%4];" \
        : "=r"(r0), "=r"(r1), "=r"(r2), "=r"(r3) : "r"(addr))

#define LDSM_X4T(r0, r1, r2, r3, addr) \
    asm volatile("ldmatrix.sync.aligned.m8n8.x4.trans.shared.b16 {%0,%1,%2,%3}, [%4];" \
        : "=r"(r0), "=r"(r1), "=r"(r2), "=r"(r3) : "r"(addr))

#define MMA_FP16(d, a, b0, b1) \
    asm volatile("mma.sync.aligned.m16n8k16.row.col.f32.f16.f16.f32 " \
        "{%0,%1,%2,%3}, {%4,%5,%6,%7}, {%8,%9}, {%0,%1,%2,%3};" \
        : "+f"((d)[0]), "+f"((d)[1]), "+f"((d)[2]), "+f"((d)[3]) \
        : "r"((a)[0]), "r"((a)[1]), "r"((a)[2]), "r"((a)[3]), "r"(b0), "r"(b1))

#define CP_WAIT(n) asm volatile("cp.async.wait_group %0;" :: "n"(n) : "memory")

// 64KB weight chunk copy, 256-thread kernels
__device__ __forceinline__ void cp_w(uint32_t dsts, const unsigned char* src, int tid) {
#pragma unroll
    for (int i = 0; i < 16; i++) {
        uint32_t o = (uint32_t)(tid + 256 * i) * 16u;
        asm volatile("cp.async.cg.shared.global [%0], [%1], 16;"
                     :: "r"(dsts + o), "l"(src + o) : "memory");
    }
    asm volatile("cp.async.commit_group;" ::: "memory");
}

// 64KB weight chunk copy, 512-thread kernels
__device__ __forceinline__ void cp_w512(uint32_t dsts, const unsigned char* src, int tid) {
#pragma unroll
    for (int i = 0; i < 8; i++) {
        uint32_t o = (uint32_t)(tid + 512 * i) * 16u;
        asm volatile("cp.async.cg.shared.global [%0], [%1], 16;"
                     :: "r"(dsts + o), "l"(src + o) : "memory");
    }
    asm volatile("cp.async.commit_group;" ::: "memory");
}

__device__ __forceinline__ uint32_t pack_hf2(float v0, float v1) {
    __half h0 = __float2half(v0), h1 = __float2half(v1);
    return (uint32_t)__half_as_ushort(h0) | ((uint32_t)__half_as_ushort(h1) << 16);
}

// ===========================================================================
// EDGE machinery — 128x128 tile, 16 warps 4x4, warp tile 32x32, fp16 2-pass
// A slab (hi only): 2 x 16KB (k0-63, k64-127), 128 rows each.
// W chunk 64KB: [hi n0-63 16K][hi n64-127 16K][lo n0-63][lo n64-127]
// ===========================================================================
__device__ __forceinline__ void mma_chunk512(float (*acc)[4][4], uint32_t ab,
                                             uint32_t wb, int warpM, int warpN, int lane) {
    const uint32_t colbase = (uint32_t)(warpN & 1) * 64u;     // bytes within slab
    const uint32_t wslab   = (uint32_t)(warpN >> 1) * 16384u;
#pragma unroll
    for (int s = 0; s < 8; s++) {
        uint32_t a[2][4];
#pragma unroll
        for (int mi = 0; mi < 2; mi++) {
            int row = warpM * 32 + mi * 16 + (lane & 15);
            uint32_t off = ((uint32_t)(row >> 3) << 10) + ((uint32_t)(row & 7) << 7)
                         + (uint32_t)((s & 3) * 32 + ((lane >> 4) << 4));
            off ^= (off >> 3) & 0x70;
            LDSM_X4(a[mi][0], a[mi][1], a[mi][2], a[mi][3],
                    ab + (uint32_t)(s >> 2) * 16384u + off);
        }
        int k = s * 16 + (lane & 15);
        uint32_t koff = ((uint32_t)(k >> 3) << 10) + ((uint32_t)(k & 7) << 7)
                      + ((uint32_t)(lane >> 4) << 4);
#pragma unroll
        for (int pass = 0; pass < 2; pass++) {
            uint32_t bb = wb + (uint32_t)pass * 32768u + wslab;
            uint32_t b[2][4];
#pragma unroll
            for (int bt = 0; bt < 2; bt++) {
                uint32_t off = koff + colbase + (uint32_t)bt * 32u;
                off ^= (off >> 3) & 0x70;
                LDSM_X4T(b[bt][0], b[bt][1], b[bt][2], b[bt][3], bb + off);
            }
#pragma unroll
            for (int mi = 0; mi < 2; mi++)
#pragma unroll
                for (int nt = 0; nt < 4; nt++)
                    MMA_FP16(acc[mi][nt], a[mi], b[nt >> 1][(nt & 1) * 2],
                             b[nt >> 1][(nt & 1) * 2 + 1]);
        }
    }
}

// edge layer epilogue: relu(acc+bias) -> fp16 -> A slabs (hi only). Zeros acc.
__device__ __forceinline__ void epi_act512(float (*acc)[4][4], uint8_t* abase,
                                           const float* bias, int warpM, int warpN, int lane) {
#pragma unroll
    for (int mi = 0; mi < 2; mi++) {
#pragma unroll
        for (int nt = 0; nt < 4; nt++) {
            int r0 = warpM * 32 + mi * 16 + (lane >> 2);
            int n  = warpN * 32 + nt * 8 + (lane & 3) * 2;
            uint32_t slab = (uint32_t)(n >> 6) * 16384u;
            uint32_t kk = (uint32_t)(n & 63);
            float b0v = bias[n], b1v = bias[n + 1];
#pragma unroll
            for (int hh = 0; hh < 2; hh++) {
                int r = r0 + hh * 8;
                float v0 = fmaxf(acc[mi][nt][hh * 2 + 0] + b0v, 0.f);
                float v1 = fmaxf(acc[mi][nt][hh * 2 + 1] + b1v, 0.f);
                uint32_t off = ((uint32_t)(r >> 3) << 10) + ((uint32_t)(r & 7) << 7)
                             + kk * 2;
                off ^= (off >> 3) & 0x70;
                *(uint32_t*)(abase + slab + off) = pack_hf2(v0, v1);
            }
            acc[mi][nt][0] = 0.f; acc[mi][nt][1] = 0.f;
            acc[mi][nt][2] = 0.f; acc[mi][nt][3] = 0.f;
        }
    }
}

// Stage a K=128 edge activation chunk: fp32 -> fp16 (hi only), 512 threads.
__device__ __forceinline__ void stage_A512(uint8_t* smb, uint32_t of_a,
                                           const float* __restrict__ hE,
                                           size_t e0, int kc, int tid) {
#pragma unroll
    for (int it = 0; it < 8; it++) {
        int idx = tid + 512 * it;           // 0..4095 (128 rows x 32 float4)
        int r = idx >> 5, c4 = idx & 31;
        float4 v = *(const float4*)(hE + (e0 + r) * KIN + kc + c4 * 4);
        uint32_t hA = pack_hf2(v.x, v.y);
        uint32_t hB = pack_hf2(v.z, v.w);
        uint32_t off = ((uint32_t)(r >> 3) << 10) + ((uint32_t)(r & 7) << 7)
                     + ((uint32_t)(c4 & 15) << 3);
        off ^= (off >> 3) & 0x70;
        uint32_t slab = (uint32_t)(c4 >> 4) * 16384;
        *(uint2*)(smb + of_a + slab + off) = make_uint2(hA, hB);
    }
}

// ===========================================================================
// NODE machinery — 64x128 tile, warps 2x4 (validated R15, unchanged)
// ===========================================================================
__device__ __forceinline__ void mma_chunk64(float (*acc)[4][4], uint32_t ab,
                                            uint32_t wb, int warpM, int warpN, int lane) {
    const uint32_t colbase = (uint32_t)(warpN & 1) * 64u;
    const uint32_t wslab   = (uint32_t)(warpN >> 1) * 16384u;
#pragma unroll
    for (int s = 0; s < 8; s++) {
        uint32_t a[2][4];
#pragma unroll
        for (int mi = 0; mi < 2; mi++) {
            int row = warpM * 32 + mi * 16 + (lane & 15);
            uint32_t off = ((uint32_t)(row >> 3) << 10) + ((uint32_t)(row & 7) << 7)
                         + (uint32_t)((s & 3) * 32 + ((lane >> 4) << 4));
            off ^= (off >> 3) & 0x70;
            LDSM_X4(a[mi][0], a[mi][1], a[mi][2], a[mi][3],
                    ab + (uint32_t)(s >> 2) * 8192u + off);
        }
        int k = s * 16 + (lane & 15);
        uint32_t koff = ((uint32_t)(k >> 3) << 10) + ((uint32_t)(k & 7) << 7)
                      + ((uint32_t)(lane >> 4) << 4);
#pragma unroll
        for (int pass = 0; pass < 2; pass++) {
            uint32_t bb = wb + (uint32_t)pass * 32768u + wslab;
            uint32_t b[2][4];
#pragma unroll
            for (int bt = 0; bt < 2; bt++) {
                uint32_t off = koff + colbase + (uint32_t)bt * 32u;
                off ^= (off >> 3) & 0x70;
                LDSM_X4T(b[bt][0], b[bt][1], b[bt][2], b[bt][3], bb + off);
            }
#pragma unroll
            for (int mi = 0; mi < 2; mi++)
#pragma unroll
                for (int nt = 0; nt < 4; nt++)
                    MMA_FP16(acc[mi][nt], a[mi], b[nt >> 1][(nt & 1) * 2],
                             b[nt >> 1][(nt & 1) * 2 + 1]);
        }
    }
}

__device__ __forceinline__ void epi_act64(float (*acc)[4][4], uint8_t* thi,
                                          const float* bias, int warpM, int warpN, int lane) {
#pragma unroll
    for (int mi = 0; mi < 2; mi++) {
#pragma unroll
        for (int nt = 0; nt < 4; nt++) {
            int r0 = warpM * 32 + mi * 16 + (lane >> 2);
            int n  = warpN * 32 + nt * 8 + (lane & 3) * 2;
            uint32_t slab = (uint32_t)(n >> 6) * 8192u;
            uint32_t kk = (uint32_t)(n & 63);
            float b0v = bias[n], b1v = bias[n + 1];
#pragma unroll
            for (int hh = 0; hh < 2; hh++) {
                int r = r0 + hh * 8;
                float v0 = fmaxf(acc[mi][nt][hh * 2 + 0] + b0v, 0.f);
                float v1 = fmaxf(acc[mi][nt][hh * 2 + 1] + b1v, 0.f);
                uint32_t off = ((uint32_t)(r >> 3) << 10) + ((uint32_t)(r & 7) << 7) + kk * 2;
                off ^= (off >> 3) & 0x70;
                *(uint32_t*)(thi + slab + off) = pack_hf2(v0, v1);
            }
        }
    }
}

// ===========================================================================
__global__ void zero_dh_kernel() {
    size_t i = (size_t)blockIdx.x * blockDim.x + threadIdx.x;
    if (i < (size_t)NND * HH / 4)
        ((float4*)g_dh)[i] = make_float4(0.f, 0.f, 0.f, 0.f);
}

// Edge weights: fp16 hi/lo [k][n] slabs, SW128 swizzled.
// Chunks: 0=W1[k0:128), 1=W1[k128:256), 2=W2, 3=W3. 64KB/chunk.
__global__ void prep_w_kernel(const float* __restrict__ W1,
                              const float* __restrict__ W2,
                              const float* __restrict__ W3) {
    int t = blockIdx.x * 256 + threadIdx.x;      // 0..65535
    int c  = t >> 14;
    int r  = t & 16383;
    int n  = r & 127;
    int kl = r >> 7;
    const float* W; int kg;
    if      (c == 0) { W = W1; kg = kl; }
    else if (c == 1) { W = W1; kg = kl + 128; }
    else if (c == 2) { W = W2; kg = kl; }
    else             { W = W3; kg = kl; }
    float w = W[(size_t)kg * 128 + n];
    __half hi = __float2half(w);
    __half lo = __float2half(w - __half2float(hi));
    int slab = n >> 6, nn = n & 63;
    uint32_t off = ((uint32_t)(kl >> 3) << 10) + ((uint32_t)(kl & 7) << 7) + nn * 2;
    off ^= (off >> 3) & 0x70;
    size_t base = (size_t)c * 65536 + (size_t)slab * 16384 + off;
    *(__half*)(g_wprep + base) = hi;
    *(__half*)(g_wprep + base + 32768) = lo;
}

// Node weights: D1 (4 chunks over n), then D2 (4 chunks over k). 64KB/chunk.
__global__ void prep_nw_kernel(const float* __restrict__ D1,
                               const float* __restrict__ D2) {
    int t = blockIdx.x * 256 + threadIdx.x;      // 0..131071
    int mat = t >> 16;
    int r   = t & 65535;
    int c   = r >> 14;
    int e   = r & 16383;
    int n   = e & 127;
    int kl  = e >> 7;
    float w;
    if (mat == 0) w = D1[(size_t)kl * FF + c * 128 + n];
    else          w = D2[(size_t)(c * 128 + kl) * HH + n];
    __half hi = __float2half(w);
    __half lo = __float2half(w - __half2float(hi));
    int slab = n >> 6, nn = n & 63;
    uint32_t off = ((uint32_t)(kl >> 3) << 10) + ((uint32_t)(kl & 7) << 7) + nn * 2;
    off ^= (off >> 3) & 0x70;
    size_t base = (size_t)mat * 262144 + (size_t)c * 65536 + (size_t)slab * 16384 + off;
    *(__half*)(g_nwprep + base) = hi;
    *(__half*)(g_nwprep + base + 32768) = lo;
}

// SMEM offsets — edge kernel (~163KB/CTA, occ 1, 512 threads)
#define OF_SRC  0
#define OF_BIAS 512
#define OF_A    2048           // hi only: [slab0 16K][slab1 16K]
#define OF_W0   34816
#define OF_W1   100352
#define SM_EDGE (165888 + 128)

// ===========================================================================
// Edge kernel: fused 3-layer MLP on HMMA (fp16 2-pass), 16 warps
// ===========================================================================
__global__ __launch_bounds__(512, 1)
void edge_mma_kernel(const float* __restrict__ hE, const int* __restrict__ eidx,
                     const float* __restrict__ b1, const float* __restrict__ b2,
                     const float* __restrict__ b3)
{
    extern __shared__ __align__(16) uint8_t sm8[];
    uint32_t sbr = smem_u32(sm8);
    uint32_t sb  = (sbr + 127u) & ~127u;
    uint8_t* smb = sm8 + (sb - sbr);

    const int tid = threadIdx.x, wid = tid >> 5, lane = tid & 31;
    const int warpM = wid & 3, warpN = wid >> 2;     // 4 x 4 warp grid
    const size_t e0 = (size_t)blockIdx.x * TE;

    if (tid < 128) {
        ((int*)(smb + OF_SRC))[tid] = eidx[e0 + tid];       // row 0 = src
        float* bs = (float*)(smb + OF_BIAS);
        bs[tid] = b1[tid]; bs[128 + tid] = b2[tid]; bs[256 + tid] = b3[tid];
    }

    cp_w512(sb + OF_W0, g_wprep, tid);              // G0: W1 chunk k0-127
    cp_w512(sb + OF_W1, g_wprep + 65536, tid);      // G1: W1 chunk k128-255

    stage_A512(smb, OF_A, hE, e0, 0, tid);
    CP_WAIT(1);
    __syncthreads();

    float acc[2][4][4];
#pragma unroll
    for (int mi = 0; mi < 2; mi++)
#pragma unroll
        for (int nt = 0; nt < 4; nt++)
#pragma unroll
            for (int q = 0; q < 4; q++) acc[mi][nt][q] = 0.f;

    const float* bias_sm = (const float*)(smb + OF_BIAS);

    // ---- layer 1, chunk 0 ----
    mma_chunk512(acc, sb + OF_A, sb + OF_W0, warpM, warpN, lane);
    __syncthreads();

    // ---- layer 1, chunk 1 ----
    cp_w512(sb + OF_W0, g_wprep + 131072, tid);     // G2: W2 into buf0
    stage_A512(smb, OF_A, hE, e0, 128, tid);
    CP_WAIT(1);                                     // G1 done (G2 may pend)
    __syncthreads();
    mma_chunk512(acc, sb + OF_A, sb + OF_W1, warpM, warpN, lane);
    __syncthreads();

    epi_act512(acc, smb + OF_A, bias_sm, warpM, warpN, lane);
    cp_w512(sb + OF_W1, g_wprep + 196608, tid);     // G3: W3 into buf1
    CP_WAIT(1);                                     // G2 done
    __syncthreads();

    // ---- layer 2 ----
    mma_chunk512(acc, sb + OF_A, sb + OF_W0, warpM, warpN, lane);
    __syncthreads();
    epi_act512(acc, smb + OF_A, bias_sm + 128, warpM, warpN, lane);
    CP_WAIT(0);                                     // G3 done
    __syncthreads();

    // ---- layer 3 ----
    mma_chunk512(acc, sb + OF_A, sb + OF_W1, warpM, warpN, lane);

    // scatter epilogue: (acc + b3) * SINV -> red.v2 into g_dh[src]
    const int* s_src = (const int*)(smb + OF_SRC);
    const float* b3s = bias_sm + 256;
#pragma unroll
    for (int mi = 0; mi < 2; mi++) {
#pragma unroll
        for (int nt = 0; nt < 4; nt++) {
            int r0 = warpM * 32 + mi * 16 + (lane >> 2);
            int n  = warpN * 32 + nt * 8 + (lane & 3) * 2;
            float bb0 = b3s[n], bb1 = b3s[n + 1];
#pragma unroll
            for (int hh = 0; hh < 2; hh++) {
                int r = r0 + hh * 8;
                int srcn = s_src[r];
                float v0 = (acc[mi][nt][hh * 2 + 0] + bb0) * SINV;
                float v1 = (acc[mi][nt][hh * 2 + 1] + bb1) * SINV;
                float* dst = g_dh + (size_t)srcn * HH + n;
                asm volatile("red.global.add.v2.f32 [%0], {%1, %2};"
                             :: "l"(dst), "f"(v0), "f"(v1) : "memory");
            }
        }
    }
}

// ===========================================================================
// Node kernel on HMMA, M=64 tile, fp16 2-pass (validated R15, unchanged)
// ===========================================================================
#define N_OF_A    0            // A hi 16K (2x8K slabs); A lo (residual) at +16384
#define N_OF_T    32768        // T hi 16K (2x8K slabs)
#define N_OF_W0   49152        // 64K: D1 chunks
#define N_OF_W1   114688       // 64K: D2 chunks; Z overlays (dead phases)
#define N_OF_Z    114688       // fp32 [64][132] = 33792
#define N_OF_MU   180224
#define N_OF_RS   180480
#define N_OF_DB1  180736       // 512 floats
#define N_OF_DB2  182784
#define N_OF_G1   183296
#define N_OF_BE1  183808
#define N_OF_G2   184320
#define N_OF_BE2  184832
#define SM_NODE   (185344 + 128)
#define LDZ 132

__global__ __launch_bounds__(256, 1)
void node_mma64_kernel(const float* __restrict__ hV,
                       const float* __restrict__ db1, const float* __restrict__ db2,
                       const float* __restrict__ g1, const float* __restrict__ be1,
                       const float* __restrict__ g2, const float* __restrict__ be2,
                       float* __restrict__ out)
{
    extern __shared__ __align__(16) uint8_t sm8[];
    uint32_t sbr = smem_u32(sm8);
    uint32_t sb  = (sbr + 127u) & ~127u;
    uint8_t* smb = sm8 + (sb - sbr);

    const int tid = threadIdx.x, wid = tid >> 5, lane = tid & 31;
    const int warpM = wid & 1, warpN = wid >> 1;     // 2 x 4 warp grid
    const int n0 = blockIdx.x * 64;
    const int nrem = min(64, NND - n0);

    float* Z    = (float*)(smb + N_OF_Z);
    float* s_mu = (float*)(smb + N_OF_MU);
    float* s_rs = (float*)(smb + N_OF_RS);
    float* db1s = (float*)(smb + N_OF_DB1);
    float* db2s = (float*)(smb + N_OF_DB2);
    float* g1s  = (float*)(smb + N_OF_G1);
    float* be1s = (float*)(smb + N_OF_BE1);
    float* g2s  = (float*)(smb + N_OF_G2);
    float* be2s = (float*)(smb + N_OF_BE2);

    cp_w(sb + N_OF_W0, g_nwprep, tid);               // G0: D1 c0

    db1s[tid] = db1[tid]; db1s[256 + tid] = db1[256 + tid];
    if (tid < 128) {
        db2s[tid] = db2[tid];
        g1s[tid] = g1[tid]; be1s[tid] = be1[tid];
        g2s[tid] = g2[tid]; be2s[tid] = be2[tid];
    }

    // phase 1: Z = hV + dh  (64 rows)
#pragma unroll
    for (int it = 0; it < 32; it++) {
        int idx = tid + 256 * it;
        int r = idx >> 7, c = idx & 127;
        float v = 0.f;
        if (r < nrem) {
            size_t g = (size_t)(n0 + r) * HH + c;
            v = hV[g] + g_dh[g];
        }
        Z[r * LDZ + c] = v;
    }
    __syncthreads();

    // LN1 row stats
    if (tid < 64) {
        const float* zr = Z + tid * LDZ;
        float s = 0.f;
        for (int c = 0; c < HH; c++) s += zr[c];
        float mu = s * (1.f / HH);
        float v = 0.f;
        for (int c = 0; c < HH; c++) { float d = zr[c] - mu; v += d * d; }
        s_mu[tid] = mu;
        s_rs[tid] = rsqrtf(v * (1.f / HH) + 1e-5f);
    }
    __syncthreads();

    // h = LN1(z) -> A hi slabs (MMA) + lo slabs (exact residual)
#pragma unroll
    for (int it = 0; it < 16; it++) {
        int idx = tid + 256 * it;        // 0..4095 pairs
        int r = idx >> 6, c = (idx & 63) * 2;
        float mu = s_mu[r], rs = s_rs[r];
        float v0 = (Z[r * LDZ + c]     - mu) * rs * g1s[c]     + be1s[c];
        float v1 = (Z[r * LDZ + c + 1] - mu) * rs * g1s[c + 1] + be1s[c + 1];
        __half h0 = __float2half(v0), h1 = __float2half(v1);
        uint32_t hp = (uint32_t)__half_as_ushort(h0)
                    | ((uint32_t)__half_as_ushort(h1) << 16);
        uint32_t lp = pack_hf2(v0 - __half2float(h0), v1 - __half2float(h1));
        uint32_t slab = (uint32_t)(c >> 6) * 8192;
        uint32_t kk = (uint32_t)(c & 63);
        uint32_t off = ((uint32_t)(r >> 3) << 10) + ((uint32_t)(r & 7) << 7) + kk * 2;
        off ^= (off >> 3) & 0x70;
        *(uint32_t*)(smb + N_OF_A + slab + off) = hp;
        *(uint32_t*)(smb + N_OF_A + 16384 + slab + off) = lp;
    }
    __syncthreads();     // Z dead; W1 region may now be written

    float acc2[2][4][4];
#pragma unroll
    for (int mi = 0; mi < 2; mi++)
#pragma unroll
        for (int nt = 0; nt < 4; nt++)
#pragma unroll
            for (int q = 0; q < 4; q++) acc2[mi][nt][q] = 0.f;

    // FFN: 4 q-chunks of 128, double-buffered weights (W0=D1, W1=D2)
    for (int qc = 0; qc < 4; qc++) {
        cp_w(sb + N_OF_W1, g_nwprep + 262144 + (size_t)qc * 65536, tid);  // D2[qc]
        CP_WAIT(1);                      // D1[qc] in W0 ready
        __syncthreads();

        float acc1[2][4][4];
#pragma unroll
        for (int mi = 0; mi < 2; mi++)
#pragma unroll
            for (int nt = 0; nt < 4; nt++)
#pragma unroll
                for (int q = 0; q < 4; q++) acc1[mi][nt][q] = 0.f;

        mma_chunk64(acc1, sb + N_OF_A, sb + N_OF_W0, warpM, warpN, lane);
        __syncthreads();                 // W0 reads done before refill

        epi_act64(acc1, smb + N_OF_T, db1s + qc * 128, warpM, warpN, lane);
        if (qc < 3) {
            cp_w(sb + N_OF_W0, g_nwprep + (size_t)(qc + 1) * 65536, tid);  // D1[qc+1]
            CP_WAIT(1);                  // D2[qc] in W1 ready
        } else {
            CP_WAIT(0);
        }
        __syncthreads();                 // T visible + W1 ready

        mma_chunk64(acc2, sb + N_OF_T, sb + N_OF_W1, warpM, warpN, lane);
        __syncthreads();                 // W1 reads done before next D2 copy
    }

    // y = h + dh2 + db2 -> Z (W1 region dead again); h exact from hi+lo
#pragma unroll
    for (int mi = 0; mi < 2; mi++) {
#pragma unroll
        for (int nt = 0; nt < 4; nt++) {
            int r0 = warpM * 32 + mi * 16 + (lane >> 2);
            int n  = warpN * 32 + nt * 8 + (lane & 3) * 2;
            float bb0 = db2s[n], bb1 = db2s[n + 1];
            uint32_t slab = (uint32_t)(n >> 6) * 8192;
            uint32_t kk = (uint32_t)(n & 63);
#pragma unroll
            for (int hh = 0; hh < 2; hh++) {
                int r = r0 + hh * 8;
                uint32_t off = ((uint32_t)(r >> 3) << 10) + ((uint32_t)(r & 7) << 7) + kk * 2;
                off ^= (off >> 3) & 0x70;
                uint32_t hp = *(uint32_t*)(smb + N_OF_A + slab + off);
                uint32_t lp = *(uint32_t*)(smb + N_OF_A + 16384 + slab + off);
                float h0 = __half2float(__ushort_as_half((unsigned short)(hp & 0xFFFF)))
                         + __half2float(__ushort_as_half((unsigned short)(lp & 0xFFFF)));
                float h1 = __half2float(__ushort_as_half((unsigned short)(hp >> 16)))
                         + __half2float(__ushort_as_half((unsigned short)(lp >> 16)));
                Z[r * LDZ + n]     = h0 + acc2[mi][nt][hh * 2 + 0] + bb0;
                Z[r * LDZ + n + 1] = h1 + acc2[mi][nt][hh * 2 + 1] + bb1;
            }
        }
    }
    __syncthreads();

    // LN2 row stats
    if (tid < 64) {
        const float* zr = Z + tid * LDZ;
        float s = 0.f;
        for (int c = 0; c < HH; c++) s += zr[c];
        float mu = s * (1.f / HH);
        float v = 0.f;
        for (int c = 0; c < HH; c++) { float d = zr[c] - mu; v += d * d; }
        s_mu[tid] = mu;
        s_rs[tid] = rsqrtf(v * (1.f / HH) + 1e-5f);
    }
    __syncthreads();

#pragma unroll
    for (int it = 0; it < 32; it++) {
        int idx = tid + 256 * it;
        int r = idx >> 7, c = idx & 127;
        if (r < nrem)
            out[(size_t)(n0 + r) * HH + c] =
                (Z[r * LDZ + c] - s_mu[r]) * s_rs[r] * g2s[c] + be2s[c];
    }
}

// ===========================================================================
extern "C" void kernel_launch(void* const* d_in, const int* in_sizes, int n_in,
                              void* d_out, int out_size)
{
    const float* hV   = (const float*)d_in[0];
    const float* hE   = (const float*)d_in[1];
    const int*   eidx = (const int*)d_in[2];   // int32 [2, NE]; row 0 = src
    const float* W1  = (const float*)d_in[3];
    const float* b1  = (const float*)d_in[4];
    const float* W2  = (const float*)d_in[5];
    const float* b2  = (const float*)d_in[6];
    const float* W3  = (const float*)d_in[7];
    const float* b3  = (const float*)d_in[8];
    const float* D1  = (const float*)d_in[9];
    const float* db1 = (const float*)d_in[10];
    const float* D2  = (const float*)d_in[11];
    const float* db2 = (const float*)d_in[12];
    const float* g1  = (const float*)d_in[13];
    const float* be1 = (const float*)d_in[14];
    const float* g2  = (const float*)d_in[15];
    const float* be2 = (const float*)d_in[16];
    float* out = (float*)d_out;

    cudaFuncSetAttribute(edge_mma_kernel, cudaFuncAttributeMaxDynamicSharedMemorySize,
                         SM_EDGE);
    cudaFuncSetAttribute(node_mma64_kernel, cudaFuncAttributeMaxDynamicSharedMemorySize,
                         SM_NODE);

    zero_dh_kernel<<<(NND * HH / 4 + 255) / 256, 256>>>();
    prep_w_kernel<<<256, 256>>>(W1, W2, W3);
    prep_nw_kernel<<<512, 256>>>(D1, D2);
    edge_mma_kernel<<<NE / TE, 512, SM_EDGE>>>(hE, eidx, b1, b2, b3);
    node_mma64_kernel<<<(NND + 63) / 64, 256, SM_NODE>>>(hV, db1, db2,
                                                         g1, be1, g2, be2, out);
}